// round 16
// baseline (speedup 1.0000x reference)
#include <cuda_runtime.h>
#include <cstdint>

// Problem constants
#define N_NODES 8192
#define T_DIM   256
#define F_DIM   128
#define C_DIM   32
#define NT_TOT  (N_NODES * T_DIM)
#define MAXDEG  512
#define CMPDEG  256
#define LN_EPS  1e-5f
#define WSTRIDE 260

// ---------------- device scratch ----------------
__device__ float g_W1[C_DIM * T_DIM];
__device__ float g_W2[C_DIM * T_DIM];
__device__ float g_bS[C_DIM];
__device__ float g_w1sum[C_DIM];
__device__ float g_w2sum[C_DIM];
__device__ float g_stats[2];
__device__ float g_part[2048];
__device__ int   g_arr1 = 0;
__device__ int   g_arr2 = 0;
__device__ float g_P[N_NODES * C_DIM];      // X @ W1^T (raw, no LN)
__device__ float g_Q[N_NODES * C_DIM];      // X @ W2^T (raw, no LN)
__device__ int   g_nz[(size_t)N_NODES * MAXDEG];
__device__ int   g_cnt[N_NODES];
__device__ float g_dinv[N_NODES];
__device__ float g_nsq[N_NODES];
__device__ float g_s[N_NODES * C_DIM];
__device__ float g_w[N_NODES * C_DIM];      // dinv_j * s_j
__device__ float g_rownum[N_NODES];
__device__ float g_rowden[N_NODES];
__device__ float g_sspart[1024 * C_DIM];

// ---------------- kW: weight folding (65 blocks) ----------------
__global__ void kW(const float* __restrict__ Wrel,
                   const float* __restrict__ brel,
                   const float* __restrict__ Wroot,
                   const float* __restrict__ Wmlp,
                   const float* __restrict__ bmlp) {
    int tid = threadIdx.x;
    int b = blockIdx.x;

    if (b < 64) {
        int o = b * 256 + tid;
        int m = o >> 13;
        int r = o & 8191;
        int c = r >> 8;
        int t = r & 255;
        const float* Wx = m ? Wroot : Wrel;
        float acc = 0.f;
        #pragma unroll 8
        for (int f = 0; f < F_DIM; f++)
            acc += Wmlp[c * F_DIM + f] * Wx[f * T_DIM + t];
        if (m) g_W2[c * T_DIM + t] = acc;
        else   g_W1[c * T_DIM + t] = acc;
        return;
    }
    // block 64: bS, w1sum, w2sum
    __shared__ float rs[256];
    __shared__ float WmT[128 * 33];
    int lane = tid & 31, w = tid >> 5;
    for (int o = tid; o < 4096; o += 256) {
        int c = o >> 7, f = o & 127;
        WmT[f * 33 + c] = Wmlp[o];
    }
    const float* src = (w < 4) ? Wrel : Wroot;
    int rbase = (w & 3) * 32;
    for (int r = rbase; r < rbase + 32; r++) {
        float a = 0.f;
        for (int t2 = lane; t2 < T_DIM; t2 += 32) a += src[r * T_DIM + t2];
        for (int o = 16; o > 0; o >>= 1) a += __shfl_xor_sync(0xffffffffu, a, o);
        if (lane == 0) rs[(w < 4 ? 0 : 128) + r] = a;
    }
    __syncthreads();
    if (tid < 96) {
        int c = tid & 31, which = tid >> 5;
        float a = 0.f;
        if (which == 2) {
            for (int f = 0; f < F_DIM; f++) a += WmT[f * 33 + c] * brel[f];
            g_bS[c] = a + bmlp[c];
        } else {
            const float* rsp = rs + which * 128;
            for (int f = 0; f < F_DIM; f++) a += WmT[f * 33 + c] * rsp[f];
            if (which) g_w2sum[c] = a; else g_w1sum[c] = a;
        }
    }
}

// ---------------- kStats: X mean/var (1024 blocks, last finalizes) ----------------
__global__ void kStats(const float* __restrict__ X) {
    int tid = threadIdx.x;
    int bid = blockIdx.x;
    int g = bid * 256 + tid;
    float s = 0.f, q = 0.f;
    for (int k = g; k < NT_TOT; k += 1024 * 256) {
        float x = X[k];
        s += x; q += x * x;
    }
    __shared__ float ss[256], sq[256];
    ss[tid] = s; sq[tid] = q;
    __syncthreads();
    for (int o = 128; o > 0; o >>= 1) {
        if (tid < o) { ss[tid] += ss[tid + o]; sq[tid] += sq[tid + o]; }
        __syncthreads();
    }
    __shared__ bool isLast;
    if (tid == 0) {
        g_part[bid] = ss[0];
        g_part[1024 + bid] = sq[0];
        __threadfence();
        isLast = (atomicAdd(&g_arr1, 1) == 1023);
    }
    __syncthreads();
    if (!isLast) return;

    float a = 0.f, bb = 0.f;
    #pragma unroll
    for (int u = 0; u < 4; u++) {
        a  += g_part[tid * 4 + u];
        bb += g_part[1024 + tid * 4 + u];
    }
    ss[tid] = a; sq[tid] = bb;
    __syncthreads();
    for (int o = 128; o > 0; o >>= 1) {
        if (tid < o) { ss[tid] += ss[tid + o]; sq[tid] += sq[tid + o]; }
        __syncthreads();
    }
    if (tid == 0) {
        float mu = ss[0] / (float)NT_TOT;
        float var = sq[0] / (float)NT_TOT - mu * mu;
        g_stats[0] = mu;
        g_stats[1] = rsqrtf(var + LN_EPS);
        g_arr1 = 0;
    }
}

// ---------------- k4_raw: P = X@W1^T, Q = X@W2^T (no stats dependency) ----------------
__global__ void k4_raw(const float* __restrict__ X) {
    extern __shared__ float sm[];
    float* W1s = sm;
    float* W2s = sm + 32 * WSTRIDE;
    float* Xs  = sm + 64 * WSTRIDE;
    int tid = threadIdx.x, lane = tid & 31, w = tid >> 5;

    for (int o = tid; o < 8192; o += 256) {
        int c = o >> 8, t = o & 255;
        W1s[c * WSTRIDE + t] = g_W1[o];
        W2s[c * WSTRIDE + t] = g_W2[o];
    }
    int rbase = blockIdx.x * 32;
    const float4* xsrc = (const float4*)(X + (size_t)rbase * T_DIM);
    float4* xd = (float4*)Xs;
    for (int o = tid; o < 2048; o += 256) xd[o] = xsrc[o];
    __syncthreads();

    float aY0 = 0, aY1 = 0, aY2 = 0, aY3 = 0;
    float aZ0 = 0, aZ1 = 0, aZ2 = 0, aZ3 = 0;
    const float* x0 = Xs + (w * 4 + 0) * 256;
    const float* x1 = Xs + (w * 4 + 1) * 256;
    const float* x2 = Xs + (w * 4 + 2) * 256;
    const float* x3 = Xs + (w * 4 + 3) * 256;
    const float* w1p = W1s + lane * WSTRIDE;
    const float* w2p = W2s + lane * WSTRIDE;
    #pragma unroll 4
    for (int t = 0; t < 256; t += 4) {
        float4 w1 = *(const float4*)(w1p + t);
        float4 w2 = *(const float4*)(w2p + t);
        float4 xa = *(const float4*)(x0 + t);
        float4 xb = *(const float4*)(x1 + t);
        float4 xc = *(const float4*)(x2 + t);
        float4 xe = *(const float4*)(x3 + t);
        aY0 += xa.x*w1.x + xa.y*w1.y + xa.z*w1.z + xa.w*w1.w;
        aZ0 += xa.x*w2.x + xa.y*w2.y + xa.z*w2.z + xa.w*w2.w;
        aY1 += xb.x*w1.x + xb.y*w1.y + xb.z*w1.z + xb.w*w1.w;
        aZ1 += xb.x*w2.x + xb.y*w2.y + xb.z*w2.z + xb.w*w2.w;
        aY2 += xc.x*w1.x + xc.y*w1.y + xc.z*w1.z + xc.w*w1.w;
        aZ2 += xc.x*w2.x + xc.y*w2.y + xc.z*w2.z + xc.w*w2.w;
        aY3 += xe.x*w1.x + xe.y*w1.y + xe.z*w1.z + xe.w*w1.w;
        aZ3 += xe.x*w2.x + xe.y*w2.y + xe.z*w2.z + xe.w*w2.w;
    }
    int r0 = rbase + w * 4;
    g_P[(r0 + 0) * 32 + lane] = aY0;
    g_P[(r0 + 1) * 32 + lane] = aY1;
    g_P[(r0 + 2) * 32 + lane] = aY2;
    g_P[(r0 + 3) * 32 + lane] = aY3;
    g_Q[(r0 + 0) * 32 + lane] = aZ0;
    g_Q[(r0 + 1) * 32 + lane] = aZ1;
    g_Q[(r0 + 2) * 32 + lane] = aZ2;
    g_Q[(r0 + 3) * 32 + lane] = aZ3;
}

// ---------------- k5main: stream A + CSR + raw gather + affine + softmax ----------------
// S_i = rstd*(sumP_i + Q_i - mu*(cnt_i*w1sum + w2sum)) + bS
__global__ void __launch_bounds__(256) k5main(const float* __restrict__ A,
                                              float* __restrict__ out) {
    int i = blockIdx.x;
    int tid = threadIdx.x, lane = tid & 31, wid = tid >> 5;
    __shared__ int s_idx[MAXDEG];
    __shared__ int s_warp[8];
    __shared__ int s_total;
    __shared__ float s_red[256];

    const float4* arow = (const float4*)(A + (size_t)i * N_NODES);
    unsigned mask = 0;
    #pragma unroll
    for (int u = 0; u < 8; u++) {
        float4 v = __ldcs(&arow[u * 256 + tid]);
        unsigned bb = (v.x != 0.f) | ((v.y != 0.f) << 1) |
                      ((v.z != 0.f) << 2) | ((v.w != 0.f) << 3);
        mask |= bb << (u * 4);
    }
    int cntL = __popc(mask);

    int incl = cntL;
    for (int o = 1; o < 32; o <<= 1) {
        int n = __shfl_up_sync(0xffffffffu, incl, o);
        if (lane >= o) incl += n;
    }
    if (lane == 31) s_warp[wid] = incl;
    __syncthreads();
    if (tid < 8) {
        int wv = s_warp[tid];
        int inc = wv;
        for (int o = 1; o < 8; o <<= 1) {
            int n = __shfl_up_sync(0xffu, inc, o);
            if (tid >= o) inc += n;
        }
        if (tid == 7) s_total = inc;
        s_warp[tid] = inc - wv;
    }
    __syncthreads();

    int p = s_warp[wid] + (incl - cntL);
    unsigned m = mask;
    while (m) {
        int bb = __ffs(m) - 1;
        m &= m - 1;
        int col = ((bb >> 2) << 10) + (tid << 2) + (bb & 3);
        if (p < MAXDEG) s_idx[p++] = col;
    }
    __syncthreads();

    int total = s_total;
    if (total > MAXDEG) total = MAXDEG;
    float dinv = rsqrtf((float)total);
    if (tid == 0) { g_cnt[i] = total; g_dinv[i] = dinv; }

    for (int k = tid; k < total; k += 256)
        g_nz[(size_t)i * MAXDEG + k] = s_idx[k];

    float acc = 0.f;
    #pragma unroll 2
    for (int k = wid; k < total; k += 8) {
        int j = s_idx[k];
        acc += g_P[j * 32 + lane];
    }
    s_red[wid * 32 + lane] = acc;
    __syncthreads();

    if (tid < 32) {
        float sumP = 0.f;
        #pragma unroll
        for (int w = 0; w < 8; w++) sumP += s_red[w * 32 + tid];
        float mu = g_stats[0], rstd = g_stats[1];
        float cntf = (float)total;
        float Sv = rstd * (sumP + g_Q[i * 32 + tid]
                           - mu * (cntf * g_w1sum[tid] + g_w2sum[tid])) + g_bS[tid];
        out[(size_t)i * 32 + tid] = Sv;

        float mx = Sv;
        #pragma unroll
        for (int o = 16; o > 0; o >>= 1) mx = fmaxf(mx, __shfl_xor_sync(0xffffffffu, mx, o));
        float e = expf(Sv - mx);
        float ssum = e;
        #pragma unroll
        for (int o = 16; o > 0; o >>= 1) ssum += __shfl_xor_sync(0xffffffffu, ssum, o);
        float sv = e / ssum;
        g_s[i * 32 + tid] = sv;
        g_w[i * 32 + tid] = dinv * sv;

        float nsq = sv * sv;
        #pragma unroll
        for (int o = 16; o > 0; o >>= 1) nsq += __shfl_xor_sync(0xffffffffu, nsq, o);
        if (tid == 0) g_nsq[i] = nsq;
    }
}

// ---------------- k678: triangle + smem-staged dinv + sTs + finalize ----------------
__global__ void __launch_bounds__(256) k678(float* __restrict__ out) {
    int b = blockIdx.x;
    int tid = threadIdx.x, lane = tid & 31, w = tid >> 5;
    __shared__ float s_dinv[N_NODES];              // 32KB: whole dinv vector
    __shared__ __align__(16) int s_cmp[8][CMPDEG]; // 8KB
    __shared__ float red[256];

    // stage dinv (coalesced)
    {
        const float4* dsrc = (const float4*)g_dinv;
        float4* ddst = (float4*)s_dinv;
        for (int o = tid; o < N_NODES / 4; o += 256) ddst[o] = dsrc[o];
    }
    __syncthreads();

    int i = b * 8 + w;
    float wi = g_w[i * 32 + lane];
    float di = s_dinv[i];
    float nsqI = g_nsq[i];
    int cnt = g_cnt[i];
    const size_t base = (size_t)i * MAXDEG;

    // pass 1: full-neighbor dinv sum (LDS) + compact j<i into smem
    float accd = 0.f;
    int cLo = 0;
    for (int kk = 0; kk < cnt; kk += 32) {
        int valid = (kk + lane) < cnt;
        int idx = valid ? g_nz[base + kk + lane] : 0;
        accd += valid ? s_dinv[idx] : 0.f;
        unsigned bal = __ballot_sync(0xffffffffu, valid && (idx < i));
        if (valid && idx < i) {
            int pos = cLo + __popc(bal & ((1u << lane) - 1u));
            if (pos < CMPDEG) s_cmp[w][pos] = idx;
        }
        cLo += __popc(bal);
    }
    if (cLo > CMPDEG) cLo = CMPDEG;
    __syncwarp();

    // pass 2: halved edge walk, 8-deep ILP
    float n0 = 0.f, n1 = 0.f, n2 = 0.f, n3 = 0.f;
    float n4 = 0.f, n5 = 0.f, n6 = 0.f, n7 = 0.f;
    int g = 0;
    for (; g + 8 <= cLo; g += 8) {
        const int4* sp = (const int4*)&s_cmp[w][g];
        int4 ja = sp[0], jb = sp[1];
        n0 += g_w[ja.x * 32 + lane];
        n1 += g_w[ja.y * 32 + lane];
        n2 += g_w[ja.z * 32 + lane];
        n3 += g_w[ja.w * 32 + lane];
        n4 += g_w[jb.x * 32 + lane];
        n5 += g_w[jb.y * 32 + lane];
        n6 += g_w[jb.z * 32 + lane];
        n7 += g_w[jb.w * 32 + lane];
    }
    for (; g < cLo; g++) {
        int j = s_cmp[w][g];
        n0 += g_w[j * 32 + lane];
    }
    float sumw = (((n0 + n1) + (n2 + n3)) + ((n4 + n5) + (n6 + n7)));
    float an = wi * (2.f * sumw + wi);      // self-loop diagonal wi^2
    #pragma unroll
    for (int o = 16; o > 0; o >>= 1) {
        an   += __shfl_xor_sync(0xffffffffu, an, o);
        accd += __shfl_xor_sync(0xffffffffu, accd, o);
    }
    if (lane == 0) {
        g_rownum[i] = an;
        g_rowden[i] = di * accd * nsqI;
    }

    // ---- sTs partial ----
    int c1 = b & 31, chunk = b >> 5;
    float acc = 0.f;
    int iend = chunk * 256 + 256;
    for (int ii = chunk * 256 + w; ii < iend; ii += 8)
        acc += g_s[ii * 32 + c1] * g_s[ii * 32 + lane];
    red[tid] = acc;
    __syncthreads();
    for (int o = 128; o >= 32; o >>= 1) {
        if (tid < o) red[tid] += red[tid + o];
        __syncthreads();
    }
    if (tid < 32) g_sspart[b * 32 + tid] = red[tid];

    __shared__ bool isLast;
    if (tid == 0) {
        __threadfence();
        isLast = (atomicAdd(&g_arr2, 1) == 1023);
    }
    __syncthreads();
    if (!isLast) return;

    // ---- finalize ----
    __shared__ float sd[256];
    __shared__ float s_num, s_den, s_frob;

    float an2 = 0.f, ad2 = 0.f;
    for (int k = tid; k < N_NODES; k += 256) {
        an2 += g_rownum[k];
        ad2 += g_rowden[k];
    }
    sd[tid] = an2;
    __syncthreads();
    for (int o = 128; o > 0; o >>= 1) { if (tid < o) sd[tid] += sd[tid + o]; __syncthreads(); }
    if (tid == 0) s_num = sd[0];
    __syncthreads();
    sd[tid] = ad2;
    __syncthreads();
    for (int o = 128; o > 0; o >>= 1) { if (tid < o) sd[tid] += sd[tid + o]; __syncthreads(); }
    if (tid == 0) s_den = sd[0];
    __syncthreads();

    float ssv[4];
    float fr = 0.f;
    #pragma unroll
    for (int u = 0; u < 4; u++) {
        int e = tid * 4 + u;
        int e1 = e >> 5, e2 = e & 31;
        float v = 0.f;
        #pragma unroll
        for (int ch = 0; ch < 32; ch++)
            v += g_sspart[((ch << 5) | e1) * 32 + e2];
        ssv[u] = v;
        fr += v * v;
    }
    sd[tid] = fr;
    __syncthreads();
    for (int o = 128; o > 0; o >>= 1) { if (tid < o) sd[tid] += sd[tid + o]; __syncthreads(); }
    if (tid == 0) s_frob = sqrtf(sd[0]);
    __syncthreads();

    float dsum = 0.f;
    #pragma unroll
    for (int u = 0; u < 4; u++) {
        int e = tid * 4 + u;
        int e1 = e >> 5, e2 = e & 31;
        float diff = ssv[u] / s_frob - ((e1 == e2) ? rsqrtf((float)C_DIM) : 0.f);
        dsum += diff * diff;
    }
    sd[tid] = dsum;
    __syncthreads();
    for (int o = 128; o > 0; o >>= 1) { if (tid < o) sd[tid] += sd[tid + o]; __syncthreads(); }

    if (tid == 0) {
        out[(size_t)N_NODES * C_DIM + 0] = -(s_num / s_den);   // loss_mc
        out[(size_t)N_NODES * C_DIM + 1] = sqrtf(sd[0]);       // loss_o
        g_arr2 = 0;
    }
}

// ---------------- launch: kW->k4_raw on s1 concurrent with kStats on s0 ----------------
extern "C" void kernel_launch(void* const* d_in, const int* in_sizes, int n_in,
                              void* d_out, int out_size) {
    const float* X     = (const float*)d_in[0];
    const float* A     = (const float*)d_in[1];
    const float* Wrel  = (const float*)d_in[2];
    const float* brel  = (const float*)d_in[3];
    const float* Wroot = (const float*)d_in[4];
    const float* Wmlp  = (const float*)d_in[5];
    const float* bmlp  = (const float*)d_in[6];
    float* out = (float*)d_out;

    const int K4_SMEM = (64 * WSTRIDE + 8192) * 4;   // 99328 B

    static cudaStream_t s1 = nullptr;
    static cudaEvent_t evF = nullptr, evPQ = nullptr;
    if (s1 == nullptr) {
        cudaStreamCreateWithFlags(&s1, cudaStreamNonBlocking);
        cudaEventCreateWithFlags(&evF, cudaEventDisableTiming);
        cudaEventCreateWithFlags(&evPQ, cudaEventDisableTiming);
        cudaFuncSetAttribute(k4_raw, cudaFuncAttributeMaxDynamicSharedMemorySize, K4_SMEM);
    }

    // fork
    cudaEventRecord(evF, 0);
    cudaStreamWaitEvent(s1, evF, 0);

    // s1: weight fold -> raw GEMM (independent of stats)
    kW<<<65, 256, 0, s1>>>(Wrel, brel, Wroot, Wmlp, bmlp);
    k4_raw<<<256, 256, K4_SMEM, s1>>>(X);
    cudaEventRecord(evPQ, s1);

    // s0: X stats (concurrent with s1)
    kStats<<<1024, 256>>>(X);

    // s0: fused A pass (needs P/Q from s1 + stats from s0)
    cudaStreamWaitEvent((cudaStream_t)0, evPQ, 0);
    k5main<<<N_NODES, 256>>>(A, out);
    k678<<<1024, 256>>>(out);
}